// round 14
// baseline (speedup 1.0000x reference)
#include <cuda_runtime.h>
#include <cuda_bf16.h>
#include <cuda_fp16.h>
#include <math.h>
#include <stdint.h>

#define NN 8192
#define HH 512
#define TAU 0.8f
#define LAM 0.5f
#define EPSV 1e-8f
#define L2E 1.44269504f

#define SROWB 80
// MLP tile (128x128)
#define ABYTES (128 * SROWB)
#define STAGEB_M (2 * ABYTES)
#define SMEM_MLP 40960
// pair tile (256x128), 3-stage pipeline
#define PA_BYTES (256 * SROWB)       // 20480
#define PB_BYTES (128 * SROWB)       // 10240
#define STAGEB_P (PA_BYTES + PB_BYTES)  // 30720
#define NSTAGE 3
#define ETS 133
#define SMEM_PAIR (NSTAGE * STAGEB_P)   // 92160 (> ET 68096)

__device__ __nv_bfloat16 g_a[2 * NN * HH];
__device__ __nv_bfloat16 g_h[2 * NN * HH];
__device__ __nv_bfloat16 g_p[2 * NN * HH];
__device__ __half g_pn[2 * NN * HH];
__device__ __nv_bfloat16 g_w1[HH * HH];
__device__ __nv_bfloat16 g_w2[HH * HH];
__device__ uint32_t g_posb[(size_t)NN * (NN / 32)];
__device__ float g_rowsum[NN], g_colsum[NN], g_pmp[NN], g_psc[NN];

__device__ __forceinline__ uint32_t smem_u32(const void* p) {
    uint32_t a;
    asm("{ .reg .u64 t; cvta.to.shared.u64 t, %1; cvt.u32.u64 %0, t; }" : "=r"(a) : "l"(p));
    return a;
}
__device__ __forceinline__ void cp16(uint32_t s, const void* g) {
    asm volatile("cp.async.cg.shared.global [%0], [%1], 16;" :: "r"(s), "l"(g));
}
#define CP_COMMIT() asm volatile("cp.async.commit_group;" ::: "memory")
#define CP_WAITN(n) asm volatile("cp.async.wait_group %0;" :: "n"(n) : "memory")

#define LDSM4(R, ADDR) \
    asm volatile("ldmatrix.sync.aligned.m8n8.x4.shared.b16 {%0,%1,%2,%3}, [%4];" \
        : "=r"((R)[0]), "=r"((R)[1]), "=r"((R)[2]), "=r"((R)[3]) : "r"(ADDR))

#define MMABF(C, A, B0, B1) \
    asm volatile("mma.sync.aligned.m16n8k16.row.col.f32.bf16.bf16.f32 " \
        "{%0,%1,%2,%3},{%4,%5,%6,%7},{%8,%9},{%0,%1,%2,%3};" \
        : "+f"((C)[0]), "+f"((C)[1]), "+f"((C)[2]), "+f"((C)[3]) \
        : "r"((A)[0]), "r"((A)[1]), "r"((A)[2]), "r"((A)[3]), "r"(B0), "r"(B1))

#define MMAF16(C, A, B0, B1) \
    asm volatile("mma.sync.aligned.m16n8k16.row.col.f16.f16.f16.f16 " \
        "{%0,%1},{%2,%3,%4,%5},{%6,%7},{%0,%1};" \
        : "+r"((C)[0]), "+r"((C)[1]) \
        : "r"((A)[0]), "r"((A)[1]), "r"((A)[2]), "r"((A)[3]), "r"(B0), "r"(B1))

__device__ __forceinline__ uint32_t pk2(float a, float b) {
    __nv_bfloat162 t = __floats2bfloat162_rn(a, b);
    return *reinterpret_cast<uint32_t*>(&t);
}

// ---- bf16/f32 mainloop (MLP): 128x128, K=512, kc=32, 2-stage ----
__device__ __forceinline__ void gemm_bf16(
    uint32_t dsm32, const __nv_bfloat16* __restrict__ A,
    const __nv_bfloat16* __restrict__ B, float cacc[2][8][4]) {
    const int tid = threadIdx.x;
    const int wid = tid >> 5, lane = tid & 31;
    const int wm = wid >> 1, wn = wid & 1;
    const __nv_bfloat16* srcs[2] = {A, B};

    {
#pragma unroll
        for (int a = 0; a < 2; ++a) {
            uint32_t sb = dsm32 + a * ABYTES;
#pragma unroll
            for (int it = 0; it < 2; ++it) {
                int id = it * 256 + tid;
                int row = id >> 2, cc = id & 3;
                cp16(sb + row * SROWB + cc * 16, srcs[a] + (size_t)row * HH + cc * 8);
            }
        }
        CP_COMMIT();
    }
    const int lrow = lane & 15, lhalf = lane >> 4;

    for (int c = 0; c < 16; ++c) {
        if (c + 1 < 16) {
            const int k0 = (c + 1) * 32;
            const uint32_t st = ((c + 1) & 1) * STAGEB_M;
#pragma unroll
            for (int a = 0; a < 2; ++a) {
                uint32_t sb = dsm32 + st + a * ABYTES;
#pragma unroll
                for (int it = 0; it < 2; ++it) {
                    int id = it * 256 + tid;
                    int row = id >> 2, cc = id & 3;
                    cp16(sb + row * SROWB + cc * 16, srcs[a] + (size_t)row * HH + k0 + cc * 8);
                }
            }
            CP_COMMIT();
            CP_WAITN(1);
        } else {
            CP_WAITN(0);
        }
        __syncthreads();
        const uint32_t st = (c & 1) * STAGEB_M;
        const uint32_t ab = dsm32 + st, bb = dsm32 + st + ABYTES;
#pragma unroll
        for (int kk = 0; kk < 2; ++kk) {
            uint32_t ah[2][4];
#pragma unroll
            for (int mf = 0; mf < 2; ++mf) {
                uint32_t off = (uint32_t)((wm * 32 + mf * 16 + lrow) * SROWB + kk * 32 + lhalf * 16);
                LDSM4(ah[mf], ab + off);
            }
            uint32_t bh[4][4];
#pragma unroll
            for (int nb = 0; nb < 4; ++nb) {
                uint32_t off = (uint32_t)((wn * 64 + nb * 16 + lrow) * SROWB + kk * 32 + lhalf * 16);
                LDSM4(bh[nb], bb + off);
            }
#pragma unroll
            for (int mf = 0; mf < 2; ++mf)
#pragma unroll
                for (int nb = 0; nb < 4; ++nb) {
                    MMABF(cacc[mf][nb * 2 + 0], ah[mf], bh[nb][0], bh[nb][2]);
                    MMABF(cacc[mf][nb * 2 + 1], ah[mf], bh[nb][1], bh[nb][3]);
                }
        }
        __syncthreads();
    }
}

template <bool ELU_>
__global__ void __launch_bounds__(256, 2) mlp_kernel(
    const __nv_bfloat16* __restrict__ A, const float* __restrict__ bias,
    __nv_bfloat16* __restrict__ C, const __nv_bfloat16* __restrict__ W) {
    extern __shared__ __align__(16) char dsm[];
    __shared__ float sbias[128];
    const uint32_t dsm32 = smem_u32(dsm);
    const int tid = threadIdx.x;
    const int wid = tid >> 5, lane = tid & 31;
    const int wm = wid >> 1, wn = wid & 1;
    const int ib = blockIdx.y * 128, jb = blockIdx.x * 128;

    if (tid < 128) sbias[tid] = bias[jb + tid];

    float cacc[2][8][4] = {};
    gemm_bf16(dsm32, A + (size_t)ib * HH, W + (size_t)jb * HH, cacc);
    __syncthreads();

#pragma unroll
    for (int mf = 0; mf < 2; ++mf)
#pragma unroll
        for (int nf = 0; nf < 8; ++nf)
#pragma unroll
            for (int h = 0; h < 2; ++h) {
                int i_l = wm * 32 + mf * 16 + (lane >> 2) + h * 8;
                int j_l = wn * 64 + nf * 8 + (lane & 3) * 2;
                float x0 = cacc[mf][nf][h * 2 + 0] + sbias[j_l];
                float x1 = cacc[mf][nf][h * 2 + 1] + sbias[j_l + 1];
                if (ELU_) {
                    x0 = (x0 > 0.f) ? x0 : (__expf(x0) - 1.f);
                    x1 = (x1 > 0.f) ? x1 : (__expf(x1) - 1.f);
                }
                size_t off = (size_t)(ib + i_l) * HH + jb + j_l;
                *(uint32_t*)(C + off) = pk2(x0, x1);
            }
}

// ---- pair: 256x128 tile, f16-accum, 3-stage pipeline, two-pass epilogue ----
__global__ void __launch_bounds__(256, 2) pair_kernel() {
    extern __shared__ __align__(16) char dsm[];
    const uint32_t dsm32 = smem_u32(dsm);
    const int tid = threadIdx.x;
    const int wid = tid >> 5, lane = tid & 31;
    const int w_m = wid >> 1;                // 0..3
    const int w_n = wid & 1;                 // 0..1
    const int ib = blockIdx.y * 256, jb = blockIdx.x * 128;

    const __half* Aptr = g_pn + (size_t)ib * HH;
    const __half* Bptr = g_pn + (size_t)NN * HH + (size_t)jb * HH;

    uint32_t cacc[4][8][2] = {};

#define PAIR_LOAD(CH)                                                          \
    {                                                                          \
        const int k0 = (CH) * 32;                                              \
        const uint32_t st = ((CH) % NSTAGE) * STAGEB_P;                        \
        _Pragma("unroll") for (int it = 0; it < 6; ++it) {                     \
            int id = it * 256 + tid;                                           \
            int row = id >> 2, cc = id & 3;                                    \
            uint32_t dst;                                                      \
            const __half* src;                                                 \
            if (row < 256) {                                                   \
                dst = dsm32 + st + row * SROWB + cc * 16;                      \
                src = Aptr + (size_t)row * HH + k0 + cc * 8;                   \
            } else {                                                           \
                dst = dsm32 + st + PA_BYTES + (row - 256) * SROWB + cc * 16;   \
                src = Bptr + (size_t)(row - 256) * HH + k0 + cc * 8;           \
            }                                                                  \
            cp16(dst, src);                                                    \
        }                                                                      \
        CP_COMMIT();                                                           \
    }

    PAIR_LOAD(0)
    PAIR_LOAD(1)

    const int lrow = lane & 15, lhalf = lane >> 4;

    for (int c = 0; c < 16; ++c) {
        if (c + 2 < 16) {
            PAIR_LOAD(c + 2)
            CP_WAITN(2);
        } else if (c + 1 < 16) {
            CP_WAITN(1);
        } else {
            CP_WAITN(0);
        }
        __syncthreads();
        const uint32_t st = (c % NSTAGE) * STAGEB_P;
        const uint32_t ab = dsm32 + st, bb = dsm32 + st + PA_BYTES;
#pragma unroll
        for (int kk = 0; kk < 2; ++kk) {
            uint32_t ah[4][4];
#pragma unroll
            for (int mf = 0; mf < 4; ++mf) {
                uint32_t off = (uint32_t)((w_m * 64 + mf * 16 + lrow) * SROWB + kk * 32 + lhalf * 16);
                LDSM4(ah[mf], ab + off);
            }
            uint32_t bh[4][4];
#pragma unroll
            for (int nb = 0; nb < 4; ++nb) {
                uint32_t off = (uint32_t)((w_n * 64 + nb * 16 + lrow) * SROWB + kk * 32 + lhalf * 16);
                LDSM4(bh[nb], bb + off);
            }
#pragma unroll
            for (int mf = 0; mf < 4; ++mf)
#pragma unroll
                for (int nb = 0; nb < 4; ++nb) {
                    MMAF16(cacc[mf][nb * 2 + 0], ah[mf], bh[nb][0], bh[nb][2]);
                    MMAF16(cacc[mf][nb * 2 + 1], ah[mf], bh[nb][1], bh[nb][3]);
                }
        }
        __syncthreads();
    }
#undef PAIR_LOAD

    // ---- two-pass epilogue ----
    float* ET = (float*)dsm;
    const __half2 k2 = __floats2half2_rn(L2E / TAU, L2E / TAU);
    float cs = 0.f, ps = 0.f;

#pragma unroll
    for (int p = 0; p < 2; ++p) {
        if ((w_m >> 1) == p) {
            const int rbase = w_m * 64 - p * 128;
#pragma unroll
            for (int mf = 0; mf < 4; ++mf)
#pragma unroll
                for (int nf = 0; nf < 8; ++nf)
#pragma unroll
                    for (int r = 0; r < 2; ++r) {
                        __half2 d = *reinterpret_cast<__half2*>(&cacc[mf][nf][r]);
                        __half2 e = h2exp2(__hmul2(d, k2));
                        int i_l = rbase + mf * 16 + (lane >> 2) + r * 8;
                        int j_l = w_n * 64 + nf * 8 + (lane & 3) * 2;
                        ET[i_l * ETS + j_l] = __low2float(e);
                        ET[i_l * ETS + j_l + 1] = __high2float(e);
                    }
        }
        __syncthreads();

        if (tid < 128) {
            const int r = tid;
            const float* row = ET + r * ETS;
            float rs = 0.f, pm = 0.f;
            const size_t pb = (size_t)(ib + p * 128 + r) * (NN / 32) + (jb >> 5);
#pragma unroll
            for (int w = 0; w < 4; ++w) {
                uint32_t u = g_posb[pb + w];
#pragma unroll
                for (int b = 0; b < 32; ++b) {
                    float e = row[w * 32 + b];
                    rs += e;
                    if ((u >> b) & 1u) pm += e;
                }
            }
            atomicAdd(&g_rowsum[ib + p * 128 + r], rs);
            atomicAdd(&g_pmp[ib + p * 128 + r], pm);
        } else {
            const int cidx = tid - 128;
            const size_t pb = (size_t)(jb + cidx) * (NN / 32) + ((ib + p * 128) >> 5);
#pragma unroll
            for (int w = 0; w < 4; ++w) {
                uint32_t u = g_posb[pb + w];
#pragma unroll
                for (int b = 0; b < 32; ++b) {
                    float e = ET[(w * 32 + b) * ETS + cidx];
                    cs += e;
                    if ((u >> b) & 1u) ps += e;
                }
            }
        }
        __syncthreads();
    }
    if (tid >= 128) {
        const int cidx = tid - 128;
        atomicAdd(&g_colsum[jb + cidx], cs);
        atomicAdd(&g_psc[jb + cidx], ps);
    }
}

// ---- fused converter: z_mp, z_sc -> g_a ; W1 -> g_w1 ; W2 -> g_w2 ----
__global__ void convert_all_kernel(const float* __restrict__ z_mp,
                                   const float* __restrict__ z_sc,
                                   const float* __restrict__ W1,
                                   const float* __restrict__ W2) {
    const int ZN8 = NN * HH / 8;          // 524288
    const int WN8 = HH * HH / 8;          // 32768
    int t = blockIdx.x * blockDim.x + threadIdx.x;
    const float* src;
    __nv_bfloat16* dst;
    int local;
    if (t < ZN8) { src = z_mp; dst = g_a; local = t; }
    else if (t < 2 * ZN8) { src = z_sc; dst = g_a + (size_t)NN * HH; local = t - ZN8; }
    else if (t < 2 * ZN8 + WN8) { src = W1; dst = g_w1; local = t - 2 * ZN8; }
    else if (t < 2 * ZN8 + 2 * WN8) { src = W2; dst = g_w2; local = t - 2 * ZN8 - WN8; }
    else return;
    size_t b = (size_t)local * 8;
    float4 v0 = *(const float4*)(src + b);
    float4 v1 = *(const float4*)(src + b + 4);
    uint4 vh;
    vh.x = pk2(v0.x, v0.y); vh.y = pk2(v0.z, v0.w);
    vh.z = pk2(v1.x, v1.y); vh.w = pk2(v1.z, v1.w);
    *(uint4*)(dst + b) = vh;
}

// ---- fused zero + posbits ----
__global__ void zero_posbits_kernel(const int* __restrict__ pos) {
    size_t w = (size_t)blockIdx.x * blockDim.x + threadIdx.x;
    if (w < NN) { g_rowsum[w] = 0.f; g_colsum[w] = 0.f; g_pmp[w] = 0.f; g_psc[w] = 0.f; }
    if (w >= (size_t)NN * (NN / 32)) return;
    const int4* p = (const int4*)(pos + w * 32);
    uint32_t m = 0;
#pragma unroll
    for (int k = 0; k < 8; ++k) {
        int4 v = p[k];
        m |= (v.x != 0 ? 1u : 0u) << (4 * k);
        m |= (v.y != 0 ? 1u : 0u) << (4 * k + 1);
        m |= (v.z != 0 ? 1u : 0u) << (4 * k + 2);
        m |= (v.w != 0 ? 1u : 0u) << (4 * k + 3);
    }
    g_posb[w] = m;
}

__global__ void normf16_kernel(const __nv_bfloat16* __restrict__ z, __half* __restrict__ o) {
    const int row = blockIdx.x, t = threadIdx.x;
    const size_t base = (size_t)row * HH + t * 4;
    float v[4];
#pragma unroll
    for (int k = 0; k < 4; ++k) v[k] = __bfloat162float(z[base + k]);
    float ss = v[0] * v[0] + v[1] * v[1] + v[2] * v[2] + v[3] * v[3];
#pragma unroll
    for (int off = 16; off > 0; off >>= 1) ss += __shfl_xor_sync(0xffffffffu, ss, off);
    __shared__ float sr[4];
    if ((t & 31) == 0) sr[t >> 5] = ss;
    __syncthreads();
    const float is = rsqrtf(sr[0] + sr[1] + sr[2] + sr[3] + 1e-30f);
    __half2 h0 = __floats2half2_rn(v[0] * is, v[1] * is);
    __half2 h1 = __floats2half2_rn(v[2] * is, v[3] * is);
    *reinterpret_cast<__half2*>(o + base) = h0;
    *reinterpret_cast<__half2*>(o + base + 2) = h1;
}

__global__ void final_kernel(float* __restrict__ out) {
    int t = threadIdx.x;
    float s = 0.f;
    for (int i = t; i < NN; i += 256) {
        float lmp = logf(g_pmp[i]) - logf(g_rowsum[i] + EPSV);
        float lsc = logf(g_psc[i]) - logf(g_colsum[i] + EPSV);
        s += LAM * lmp + (1.0f - LAM) * lsc;
    }
#pragma unroll
    for (int o = 16; o > 0; o >>= 1) s += __shfl_down_sync(0xffffffffu, s, o);
    __shared__ float sr[8];
    if ((t & 31) == 0) sr[t >> 5] = s;
    __syncthreads();
    if (t == 0) {
        float tot = 0.f;
#pragma unroll
        for (int w = 0; w < 8; w++) tot += sr[w];
        out[0] = -tot / (float)NN;
    }
}

extern "C" void kernel_launch(void* const* d_in, const int* in_sizes, int n_in,
                              void* d_out, int out_size) {
    const float* z_mp = (const float*)d_in[0];
    const float* z_sc = (const float*)d_in[1];
    const int* pos = (const int*)d_in[2];
    const float* W1 = (const float*)d_in[3];
    const float* b1 = (const float*)d_in[4];
    const float* W2 = (const float*)d_in[5];
    const float* b2 = (const float*)d_in[6];

    __nv_bfloat16 *a, *h, *p, *w1, *w2;
    __half* pn;
    cudaGetSymbolAddress((void**)&a, g_a);
    cudaGetSymbolAddress((void**)&h, g_h);
    cudaGetSymbolAddress((void**)&p, g_p);
    cudaGetSymbolAddress((void**)&pn, g_pn);
    cudaGetSymbolAddress((void**)&w1, g_w1);
    cudaGetSymbolAddress((void**)&w2, g_w2);

    static bool init_done = false;
    if (!init_done) {
        cudaFuncSetAttribute(mlp_kernel<true>, cudaFuncAttributeMaxDynamicSharedMemorySize, SMEM_MLP);
        cudaFuncSetAttribute(mlp_kernel<false>, cudaFuncAttributeMaxDynamicSharedMemorySize, SMEM_MLP);
        cudaFuncSetAttribute(pair_kernel, cudaFuncAttributeMaxDynamicSharedMemorySize, SMEM_PAIR);
        init_done = true;
    }

    const int CV_T = 2 * (NN * HH / 8) + 2 * (HH * HH / 8);

    // launch order fixed so pair is the 6th launch (ncu -s 5 -c 1 captures it)
    convert_all_kernel<<<(CV_T + 255) / 256, 256>>>(z_mp, z_sc, W1, W2);           // 1
    zero_posbits_kernel<<<(NN * (NN / 32) + 255) / 256, 256>>>(pos);               // 2

    dim3 mg(HH / 128, 2 * NN / 128);
    mlp_kernel<true><<<mg, 256, SMEM_MLP>>>(a, b1, h, w1);                         // 3
    mlp_kernel<false><<<mg, 256, SMEM_MLP>>>(h, b2, p, w2);                        // 4

    normf16_kernel<<<2 * NN, 128>>>(p, pn);                                        // 5

    pair_kernel<<<dim3(NN / 128, NN / 256), 256, SMEM_PAIR>>>();                   // 6

    final_kernel<<<1, 256>>>((float*)d_out);                                       // 7
}

// round 15
// speedup vs baseline: 1.0269x; 1.0269x over previous
#include <cuda_runtime.h>
#include <cuda_bf16.h>
#include <cuda_fp16.h>
#include <math.h>
#include <stdint.h>

#define NN 8192
#define HH 512
#define TAU 0.8f
#define LAM 0.5f
#define EPSV 1e-8f
#define L2E 1.44269504f

#define SROWB 80
// MLP tile (128x128)
#define ABYTES (128 * SROWB)
#define STAGEB_M (2 * ABYTES)
#define SMEM_MLP 40960
// pair tile (256x128), 2-stage
#define PA_BYTES (256 * SROWB)
#define PB_BYTES (128 * SROWB)
#define STAGEB_P (PA_BYTES + PB_BYTES)
#define ETS 133
#define SMEM_PAIR 69632

__device__ __half g_a[2 * NN * HH];
__device__ __half g_h[2 * NN * HH];
__device__ __half g_p[2 * NN * HH];
__device__ __half g_pn[2 * NN * HH];
__device__ __half g_w1[HH * HH];
__device__ __half g_w2[HH * HH];
__device__ uint32_t g_posb[(size_t)NN * (NN / 32)];
__device__ float g_rowsum[NN], g_colsum[NN], g_pmp[NN], g_psc[NN];

__device__ __forceinline__ uint32_t smem_u32(const void* p) {
    uint32_t a;
    asm("{ .reg .u64 t; cvta.to.shared.u64 t, %1; cvt.u32.u64 %0, t; }" : "=r"(a) : "l"(p));
    return a;
}
__device__ __forceinline__ void cp16(uint32_t s, const void* g) {
    asm volatile("cp.async.cg.shared.global [%0], [%1], 16;" :: "r"(s), "l"(g));
}
#define CP_COMMIT() asm volatile("cp.async.commit_group;" ::: "memory")
#define CP_WAITN(n) asm volatile("cp.async.wait_group %0;" :: "n"(n) : "memory")

#define LDSM4(R, ADDR) \
    asm volatile("ldmatrix.sync.aligned.m8n8.x4.shared.b16 {%0,%1,%2,%3}, [%4];" \
        : "=r"((R)[0]), "=r"((R)[1]), "=r"((R)[2]), "=r"((R)[3]) : "r"(ADDR))

#define MMAF16(C, A, B0, B1) \
    asm volatile("mma.sync.aligned.m16n8k16.row.col.f16.f16.f16.f16 " \
        "{%0,%1},{%2,%3,%4,%5},{%6,%7},{%0,%1};" \
        : "+r"((C)[0]), "+r"((C)[1]) \
        : "r"((A)[0]), "r"((A)[1]), "r"((A)[2]), "r"((A)[3]), "r"(B0), "r"(B1))

__device__ __forceinline__ uint32_t pkh2(float a, float b) {
    __half2 t = __floats2half2_rn(a, b);
    return *reinterpret_cast<uint32_t*>(&t);
}

// ---- MLP: C = act(A @ W^T + b), f16 in/out, f16 accum, 3 CTAs/SM ----
template <bool ELU_>
__global__ void __launch_bounds__(256, 3) mlp_kernel(
    const __half* __restrict__ A, const float* __restrict__ bias,
    __half* __restrict__ C, const __half* __restrict__ W) {
    extern __shared__ __align__(16) char dsm[];
    __shared__ float sbias[128];
    const uint32_t dsm32 = smem_u32(dsm);
    const int tid = threadIdx.x;
    const int wid = tid >> 5, lane = tid & 31;
    const int wm = wid >> 1, wn = wid & 1;
    const int ib = blockIdx.y * 128, jb = blockIdx.x * 128;

    if (tid < 128) sbias[tid] = bias[jb + tid];

    const __half* srcs[2] = {A + (size_t)ib * HH, W + (size_t)jb * HH};
    uint32_t cacc[2][8][2] = {};

    {
#pragma unroll
        for (int a = 0; a < 2; ++a) {
            uint32_t sb = dsm32 + a * ABYTES;
#pragma unroll
            for (int it = 0; it < 2; ++it) {
                int id = it * 256 + tid;
                int row = id >> 2, cc = id & 3;
                cp16(sb + row * SROWB + cc * 16, srcs[a] + (size_t)row * HH + cc * 8);
            }
        }
        CP_COMMIT();
    }
    const int lrow = lane & 15, lhalf = lane >> 4;

    for (int c = 0; c < 16; ++c) {
        if (c + 1 < 16) {
            const int k0 = (c + 1) * 32;
            const uint32_t st = ((c + 1) & 1) * STAGEB_M;
#pragma unroll
            for (int a = 0; a < 2; ++a) {
                uint32_t sb = dsm32 + st + a * ABYTES;
#pragma unroll
                for (int it = 0; it < 2; ++it) {
                    int id = it * 256 + tid;
                    int row = id >> 2, cc = id & 3;
                    cp16(sb + row * SROWB + cc * 16, srcs[a] + (size_t)row * HH + k0 + cc * 8);
                }
            }
            CP_COMMIT();
            CP_WAITN(1);
        } else {
            CP_WAITN(0);
        }
        __syncthreads();
        const uint32_t st = (c & 1) * STAGEB_M;
        const uint32_t ab = dsm32 + st, bb = dsm32 + st + ABYTES;
#pragma unroll
        for (int kk = 0; kk < 2; ++kk) {
            uint32_t ah[2][4];
#pragma unroll
            for (int mf = 0; mf < 2; ++mf) {
                uint32_t off = (uint32_t)((wm * 32 + mf * 16 + lrow) * SROWB + kk * 32 + lhalf * 16);
                LDSM4(ah[mf], ab + off);
            }
            uint32_t bh[4][4];
#pragma unroll
            for (int nb = 0; nb < 4; ++nb) {
                uint32_t off = (uint32_t)((wn * 64 + nb * 16 + lrow) * SROWB + kk * 32 + lhalf * 16);
                LDSM4(bh[nb], bb + off);
            }
#pragma unroll
            for (int mf = 0; mf < 2; ++mf)
#pragma unroll
                for (int nb = 0; nb < 4; ++nb) {
                    MMAF16(cacc[mf][nb * 2 + 0], ah[mf], bh[nb][0], bh[nb][2]);
                    MMAF16(cacc[mf][nb * 2 + 1], ah[mf], bh[nb][1], bh[nb][3]);
                }
        }
        __syncthreads();
    }

#pragma unroll
    for (int mf = 0; mf < 2; ++mf)
#pragma unroll
        for (int nf = 0; nf < 8; ++nf)
#pragma unroll
            for (int h = 0; h < 2; ++h) {
                __half2 d = *reinterpret_cast<__half2*>(&cacc[mf][nf][h]);
                int i_l = wm * 32 + mf * 16 + (lane >> 2) + h * 8;
                int j_l = wn * 64 + nf * 8 + (lane & 3) * 2;
                float x0 = __low2float(d) + sbias[j_l];
                float x1 = __high2float(d) + sbias[j_l + 1];
                if (ELU_) {
                    x0 = (x0 > 0.f) ? x0 : (__expf(x0) - 1.f);
                    x1 = (x1 > 0.f) ? x1 : (__expf(x1) - 1.f);
                }
                size_t off = (size_t)(ib + i_l) * HH + jb + j_l;
                *(uint32_t*)(C + off) = pkh2(x0, x1);
            }
}

// ---- pair: 256x128 tile, f16-accum, 2-stage, two-pass epilogue ----
__global__ void __launch_bounds__(256, 2) pair_kernel() {
    extern __shared__ __align__(16) char dsm[];
    const uint32_t dsm32 = smem_u32(dsm);
    const int tid = threadIdx.x;
    const int wid = tid >> 5, lane = tid & 31;
    const int w_m = wid >> 1;
    const int w_n = wid & 1;
    const int ib = blockIdx.y * 256, jb = blockIdx.x * 128;

    const __half* Aptr = g_pn + (size_t)ib * HH;
    const __half* Bptr = g_pn + (size_t)NN * HH + (size_t)jb * HH;

    uint32_t cacc[4][8][2] = {};

    {
#pragma unroll
        for (int it = 0; it < 6; ++it) {
            int id = it * 256 + tid;
            int row = id >> 2, cc = id & 3;
            uint32_t dst;
            const __half* src;
            if (row < 256) {
                dst = dsm32 + row * SROWB + cc * 16;
                src = Aptr + (size_t)row * HH + cc * 8;
            } else {
                dst = dsm32 + PA_BYTES + (row - 256) * SROWB + cc * 16;
                src = Bptr + (size_t)(row - 256) * HH + cc * 8;
            }
            cp16(dst, src);
        }
        CP_COMMIT();
    }
    const int lrow = lane & 15, lhalf = lane >> 4;

    for (int c = 0; c < 16; ++c) {
        if (c + 1 < 16) {
            const int k0 = (c + 1) * 32;
            const uint32_t st = ((c + 1) & 1) * STAGEB_P;
#pragma unroll
            for (int it = 0; it < 6; ++it) {
                int id = it * 256 + tid;
                int row = id >> 2, cc = id & 3;
                uint32_t dst;
                const __half* src;
                if (row < 256) {
                    dst = dsm32 + st + row * SROWB + cc * 16;
                    src = Aptr + (size_t)row * HH + k0 + cc * 8;
                } else {
                    dst = dsm32 + st + PA_BYTES + (row - 256) * SROWB + cc * 16;
                    src = Bptr + (size_t)(row - 256) * HH + k0 + cc * 8;
                }
                cp16(dst, src);
            }
            CP_COMMIT();
            CP_WAITN(1);
        } else {
            CP_WAITN(0);
        }
        __syncthreads();
        const uint32_t st = (c & 1) * STAGEB_P;
        const uint32_t ab = dsm32 + st, bb = dsm32 + st + PA_BYTES;
#pragma unroll
        for (int kk = 0; kk < 2; ++kk) {
            uint32_t ah[4][4];
#pragma unroll
            for (int mf = 0; mf < 4; ++mf) {
                uint32_t off = (uint32_t)((w_m * 64 + mf * 16 + lrow) * SROWB + kk * 32 + lhalf * 16);
                LDSM4(ah[mf], ab + off);
            }
            uint32_t bh[4][4];
#pragma unroll
            for (int nb = 0; nb < 4; ++nb) {
                uint32_t off = (uint32_t)((w_n * 64 + nb * 16 + lrow) * SROWB + kk * 32 + lhalf * 16);
                LDSM4(bh[nb], bb + off);
            }
#pragma unroll
            for (int mf = 0; mf < 4; ++mf)
#pragma unroll
                for (int nb = 0; nb < 4; ++nb) {
                    MMAF16(cacc[mf][nb * 2 + 0], ah[mf], bh[nb][0], bh[nb][2]);
                    MMAF16(cacc[mf][nb * 2 + 1], ah[mf], bh[nb][1], bh[nb][3]);
                }
        }
        __syncthreads();
    }

    // ---- two-pass epilogue ----
    float* ET = (float*)dsm;
    const __half2 k2 = __floats2half2_rn(L2E / TAU, L2E / TAU);
    float cs = 0.f, ps = 0.f;

#pragma unroll
    for (int p = 0; p < 2; ++p) {
        if ((w_m >> 1) == p) {
            const int rbase = w_m * 64 - p * 128;
#pragma unroll
            for (int mf = 0; mf < 4; ++mf)
#pragma unroll
                for (int nf = 0; nf < 8; ++nf)
#pragma unroll
                    for (int r = 0; r < 2; ++r) {
                        __half2 d = *reinterpret_cast<__half2*>(&cacc[mf][nf][r]);
                        __half2 e = h2exp2(__hmul2(d, k2));
                        int i_l = rbase + mf * 16 + (lane >> 2) + r * 8;
                        int j_l = w_n * 64 + nf * 8 + (lane & 3) * 2;
                        ET[i_l * ETS + j_l] = __low2float(e);
                        ET[i_l * ETS + j_l + 1] = __high2float(e);
                    }
        }
        __syncthreads();

        if (tid < 128) {
            const int r = tid;
            const float* row = ET + r * ETS;
            float rs = 0.f, pm = 0.f;
            const size_t pb = (size_t)(ib + p * 128 + r) * (NN / 32) + (jb >> 5);
#pragma unroll
            for (int w = 0; w < 4; ++w) {
                uint32_t u = g_posb[pb + w];
#pragma unroll
                for (int b = 0; b < 32; ++b) {
                    float e = row[w * 32 + b];
                    rs += e;
                    if ((u >> b) & 1u) pm += e;
                }
            }
            atomicAdd(&g_rowsum[ib + p * 128 + r], rs);
            atomicAdd(&g_pmp[ib + p * 128 + r], pm);
        } else {
            const int cidx = tid - 128;
            const size_t pb = (size_t)(jb + cidx) * (NN / 32) + ((ib + p * 128) >> 5);
#pragma unroll
            for (int w = 0; w < 4; ++w) {
                uint32_t u = g_posb[pb + w];
#pragma unroll
                for (int b = 0; b < 32; ++b) {
                    float e = ET[(w * 32 + b) * ETS + cidx];
                    cs += e;
                    if ((u >> b) & 1u) ps += e;
                }
            }
        }
        __syncthreads();
    }
    if (tid >= 128) {
        const int cidx = tid - 128;
        atomicAdd(&g_colsum[jb + cidx], cs);
        atomicAdd(&g_psc[jb + cidx], ps);
    }
}

// ---- fused converter -> f16 ----
__global__ void convert_all_kernel(const float* __restrict__ z_mp,
                                   const float* __restrict__ z_sc,
                                   const float* __restrict__ W1,
                                   const float* __restrict__ W2) {
    const int ZN8 = NN * HH / 8;
    const int WN8 = HH * HH / 8;
    int t = blockIdx.x * blockDim.x + threadIdx.x;
    const float* src;
    __half* dst;
    int local;
    if (t < ZN8) { src = z_mp; dst = g_a; local = t; }
    else if (t < 2 * ZN8) { src = z_sc; dst = g_a + (size_t)NN * HH; local = t - ZN8; }
    else if (t < 2 * ZN8 + WN8) { src = W1; dst = g_w1; local = t - 2 * ZN8; }
    else if (t < 2 * ZN8 + 2 * WN8) { src = W2; dst = g_w2; local = t - 2 * ZN8 - WN8; }
    else return;
    size_t b = (size_t)local * 8;
    float4 v0 = *(const float4*)(src + b);
    float4 v1 = *(const float4*)(src + b + 4);
    uint4 vh;
    vh.x = pkh2(v0.x, v0.y); vh.y = pkh2(v0.z, v0.w);
    vh.z = pkh2(v1.x, v1.y); vh.w = pkh2(v1.z, v1.w);
    *(uint4*)(dst + b) = vh;
}

__global__ void zero_posbits_kernel(const int* __restrict__ pos) {
    size_t w = (size_t)blockIdx.x * blockDim.x + threadIdx.x;
    if (w < NN) { g_rowsum[w] = 0.f; g_colsum[w] = 0.f; g_pmp[w] = 0.f; g_psc[w] = 0.f; }
    if (w >= (size_t)NN * (NN / 32)) return;
    const int4* p = (const int4*)(pos + w * 32);
    uint32_t m = 0;
#pragma unroll
    for (int k = 0; k < 8; ++k) {
        int4 v = p[k];
        m |= (v.x != 0 ? 1u : 0u) << (4 * k);
        m |= (v.y != 0 ? 1u : 0u) << (4 * k + 1);
        m |= (v.z != 0 ? 1u : 0u) << (4 * k + 2);
        m |= (v.w != 0 ? 1u : 0u) << (4 * k + 3);
    }
    g_posb[w] = m;
}

__global__ void normf16_kernel(const __half* __restrict__ z, __half* __restrict__ o) {
    const int row = blockIdx.x, t = threadIdx.x;
    const size_t base = (size_t)row * HH + t * 4;
    float v[4];
#pragma unroll
    for (int k = 0; k < 4; ++k) v[k] = __half2float(z[base + k]);
    float ss = v[0] * v[0] + v[1] * v[1] + v[2] * v[2] + v[3] * v[3];
#pragma unroll
    for (int off = 16; off > 0; off >>= 1) ss += __shfl_xor_sync(0xffffffffu, ss, off);
    __shared__ float sr[4];
    if ((t & 31) == 0) sr[t >> 5] = ss;
    __syncthreads();
    const float is = rsqrtf(sr[0] + sr[1] + sr[2] + sr[3] + 1e-30f);
    __half2 h0 = __floats2half2_rn(v[0] * is, v[1] * is);
    __half2 h1 = __floats2half2_rn(v[2] * is, v[3] * is);
    *reinterpret_cast<__half2*>(o + base) = h0;
    *reinterpret_cast<__half2*>(o + base + 2) = h1;
}

__global__ void final_kernel(float* __restrict__ out) {
    int t = threadIdx.x;
    float s = 0.f;
    for (int i = t; i < NN; i += 256) {
        float lmp = logf(g_pmp[i]) - logf(g_rowsum[i] + EPSV);
        float lsc = logf(g_psc[i]) - logf(g_colsum[i] + EPSV);
        s += LAM * lmp + (1.0f - LAM) * lsc;
    }
#pragma unroll
    for (int o = 16; o > 0; o >>= 1) s += __shfl_down_sync(0xffffffffu, s, o);
    __shared__ float sr[8];
    if ((t & 31) == 0) sr[t >> 5] = s;
    __syncthreads();
    if (t == 0) {
        float tot = 0.f;
#pragma unroll
        for (int w = 0; w < 8; w++) tot += sr[w];
        out[0] = -tot / (float)NN;
    }
}

extern "C" void kernel_launch(void* const* d_in, const int* in_sizes, int n_in,
                              void* d_out, int out_size) {
    const float* z_mp = (const float*)d_in[0];
    const float* z_sc = (const float*)d_in[1];
    const int* pos = (const int*)d_in[2];
    const float* W1 = (const float*)d_in[3];
    const float* b1 = (const float*)d_in[4];
    const float* W2 = (const float*)d_in[5];
    const float* b2 = (const float*)d_in[6];

    __half *a, *h, *p, *pn, *w1, *w2;
    cudaGetSymbolAddress((void**)&a, g_a);
    cudaGetSymbolAddress((void**)&h, g_h);
    cudaGetSymbolAddress((void**)&p, g_p);
    cudaGetSymbolAddress((void**)&pn, g_pn);
    cudaGetSymbolAddress((void**)&w1, g_w1);
    cudaGetSymbolAddress((void**)&w2, g_w2);

    static bool init_done = false;
    if (!init_done) {
        cudaFuncSetAttribute(mlp_kernel<true>, cudaFuncAttributeMaxDynamicSharedMemorySize, SMEM_MLP);
        cudaFuncSetAttribute(mlp_kernel<false>, cudaFuncAttributeMaxDynamicSharedMemorySize, SMEM_MLP);
        cudaFuncSetAttribute(pair_kernel, cudaFuncAttributeMaxDynamicSharedMemorySize, SMEM_PAIR);
        init_done = true;
    }

    const int CV_T = 2 * (NN * HH / 8) + 2 * (HH * HH / 8);

    convert_all_kernel<<<(CV_T + 255) / 256, 256>>>(z_mp, z_sc, W1, W2);           // 1
    zero_posbits_kernel<<<(NN * (NN / 32) + 255) / 256, 256>>>(pos);               // 2

    dim3 mg(HH / 128, 2 * NN / 128);
    mlp_kernel<true><<<mg, 256, SMEM_MLP>>>(a, b1, h, w1);                         // 3
    mlp_kernel<false><<<mg, 256, SMEM_MLP>>>(h, b2, p, w2);                        // 4

    normf16_kernel<<<2 * NN, 128>>>(p, pn);                                        // 5

    pair_kernel<<<dim3(NN / 128, NN / 256), 256, SMEM_PAIR>>>();                   // 6

    final_kernel<<<1, 256>>>((float*)d_out);                                       // 7
}